// round 1
// baseline (speedup 1.0000x reference)
#include <cuda_runtime.h>

#define BATCH 4
#define SEQ   1024
#define DIM   1024
#define NH    16
#define HD    64

// Scratch (allocation-free contract: __device__ globals)
__device__ float g_q[BATCH * NH * SEQ * HD];     // [B,H,S,hd]
__device__ float g_k[BATCH * NH * SEQ * HD];
__device__ float g_v[BATCH * NH * SEQ * HD];
__device__ float g_ctx[BATCH * SEQ * DIM];       // [B,S,D] attention output

// ---------------------------------------------------------------------------
// Projection GEMM: A[4096x1024] @ W[1024x1024], epilogue writes head-split
// layout [B,H,S,hd]. blockIdx.z selects which of Q/K/V (all use W_q,
// faithful to the reference).
// 128x128 tile, BK=8, 256 threads, 8x8 per thread (strided micro-tiles).
// ---------------------------------------------------------------------------
__global__ __launch_bounds__(256, 2) void proj_kernel(
    const float* __restrict__ Qin, const float* __restrict__ Kin,
    const float* __restrict__ Vin, const float* __restrict__ W)
{
    const int N = DIM, K = DIM;
    const float* A;
    float* dst;
    if (blockIdx.z == 0)      { A = Qin; dst = g_q; }
    else if (blockIdx.z == 1) { A = Kin; dst = g_k; }
    else                      { A = Vin; dst = g_v; }

    __shared__ float As[8][128];
    __shared__ float Bs[8][128];

    const int tid  = threadIdx.x;
    const int tx   = tid & 15, ty = tid >> 4;
    const int arow = tid >> 1, ak = (tid & 1) << 2;
    const int brow = tid >> 5, bcol = (tid & 31) << 2;

    const float* Ap = A + (blockIdx.y * 128 + arow) * K + ak;
    const float* Bp = W + brow * N + blockIdx.x * 128 + bcol;

    float acc[8][8];
#pragma unroll
    for (int i = 0; i < 8; i++)
#pragma unroll
        for (int j = 0; j < 8; j++) acc[i][j] = 0.f;

    float4 av = *(const float4*)Ap;
    float4 bv = *(const float4*)Bp;

    const int ntiles = K >> 3;
    for (int t = 0; t < ntiles; t++) {
        As[ak + 0][arow] = av.x; As[ak + 1][arow] = av.y;
        As[ak + 2][arow] = av.z; As[ak + 3][arow] = av.w;
        *(float4*)&Bs[brow][bcol] = bv;
        __syncthreads();
        if (t + 1 < ntiles) {
            av = *(const float4*)(Ap + (t + 1) * 8);
            bv = *(const float4*)(Bp + (t + 1) * 8 * N);
        }
#pragma unroll
        for (int kk = 0; kk < 8; kk++) {
            float a[8], b[8];
#pragma unroll
            for (int i = 0; i < 8; i++) a[i] = As[kk][ty + 16 * i];
#pragma unroll
            for (int j = 0; j < 8; j++) b[j] = Bs[kk][tx + 16 * j];
#pragma unroll
            for (int i = 0; i < 8; i++)
#pragma unroll
                for (int j = 0; j < 8; j++)
                    acc[i][j] = fmaf(a[i], b[j], acc[i][j]);
        }
        __syncthreads();
    }

    // head-split epilogue
#pragma unroll
    for (int i = 0; i < 8; i++) {
        int m  = blockIdx.y * 128 + ty + 16 * i;
        int bb = m >> 10, s = m & 1023;
#pragma unroll
        for (int j = 0; j < 8; j++) {
            int n = blockIdx.x * 128 + tx + 16 * j;
            int h = n >> 6, dd = n & 63;
            dst[(((bb * NH + h) * SEQ) + s) * HD + dd] = acc[i][j];
        }
    }
}

// ---------------------------------------------------------------------------
// Output GEMM: g_ctx[4096x1024] @ W_o[1024x1024] -> d_out (plain layout).
// ---------------------------------------------------------------------------
__global__ __launch_bounds__(256, 2) void out_kernel(
    const float* __restrict__ W, float* __restrict__ C)
{
    const int N = DIM, K = DIM;
    const float* A = g_ctx;

    __shared__ float As[8][128];
    __shared__ float Bs[8][128];

    const int tid  = threadIdx.x;
    const int tx   = tid & 15, ty = tid >> 4;
    const int arow = tid >> 1, ak = (tid & 1) << 2;
    const int brow = tid >> 5, bcol = (tid & 31) << 2;

    const float* Ap = A + (blockIdx.y * 128 + arow) * K + ak;
    const float* Bp = W + brow * N + blockIdx.x * 128 + bcol;

    float acc[8][8];
#pragma unroll
    for (int i = 0; i < 8; i++)
#pragma unroll
        for (int j = 0; j < 8; j++) acc[i][j] = 0.f;

    float4 av = *(const float4*)Ap;
    float4 bv = *(const float4*)Bp;

    const int ntiles = K >> 3;
    for (int t = 0; t < ntiles; t++) {
        As[ak + 0][arow] = av.x; As[ak + 1][arow] = av.y;
        As[ak + 2][arow] = av.z; As[ak + 3][arow] = av.w;
        *(float4*)&Bs[brow][bcol] = bv;
        __syncthreads();
        if (t + 1 < ntiles) {
            av = *(const float4*)(Ap + (t + 1) * 8);
            bv = *(const float4*)(Bp + (t + 1) * 8 * N);
        }
#pragma unroll
        for (int kk = 0; kk < 8; kk++) {
            float a[8], b[8];
#pragma unroll
            for (int i = 0; i < 8; i++) a[i] = As[kk][ty + 16 * i];
#pragma unroll
            for (int j = 0; j < 8; j++) b[j] = Bs[kk][tx + 16 * j];
#pragma unroll
            for (int i = 0; i < 8; i++)
#pragma unroll
                for (int j = 0; j < 8; j++)
                    acc[i][j] = fmaf(a[i], b[j], acc[i][j]);
        }
        __syncthreads();
    }

#pragma unroll
    for (int i = 0; i < 8; i++) {
        int m = blockIdx.y * 128 + ty + 16 * i;
#pragma unroll
        for (int j = 0; j < 8; j++) {
            int n = blockIdx.x * 128 + tx + 16 * j;
            C[m * DIM + n] = acc[i][j];
        }
    }
}

// ---------------------------------------------------------------------------
// Fused flash attention with mask-aware tile skipping.
// Block = (qtile of 64 rows, head, batch); 256 threads as 16x16, each owning
// a 4x4 strided micro-tile (rows ty+16r, cols tx+16c).
// Smem: sQ[64][64] + sV[64][64] + union buffer sKS[64][64] (K swizzled / P
// plain) = 48 KB exactly.
// Keys with index >= valid_len receive weight exactly 0 in the reference
// (exp(-1e6 - max) underflows), so tiles entirely past valid_len are skipped.
// ---------------------------------------------------------------------------
__global__ __launch_bounds__(256) void attn_kernel(const int* __restrict__ vlens)
{
    const int qt = blockIdx.x, h = blockIdx.y, b = blockIdx.z;
    const int vlen = vlens[b];

    __shared__ float sQ[64][64];
    __shared__ float sKS[64][64];   // union: K (swizzled) then P (plain)
    __shared__ float sV[64][64];

    const int tid = threadIdx.x;
    const int tx = tid & 15, ty = tid >> 4;

    const float* qbase = g_q + ((b * NH + h) * SEQ + qt * 64) * HD;
    const float* kbase = g_k + ((b * NH + h) * SEQ) * HD;
    const float* vbase = g_v + ((b * NH + h) * SEQ) * HD;

    // load Q tile (persistent)
    for (int i = tid; i < 64 * 16; i += 256) {
        int row = i >> 4, c4 = (i & 15) << 2;
        *(float4*)&sQ[row][c4] = *(const float4*)(qbase + row * HD + c4);
    }

    float m_run[4], l_run[4], acc_o[4][4];
#pragma unroll
    for (int r = 0; r < 4; r++) {
        m_run[r] = -1e30f; l_run[r] = 0.f;
#pragma unroll
        for (int c = 0; c < 4; c++) acc_o[r][c] = 0.f;
    }

    const int ntiles = (vlen + 63) >> 6;
    const int swz = tx << 1;   // read-side swizzle for this thread's K columns

    for (int kt = 0; kt < ntiles; kt++) {
        __syncthreads();   // prev PV done reading sKS/sV (also covers sQ load, tile 0)

        // load K (XOR-swizzled so column reads are bank-conflict-free) and V
        for (int i = tid; i < 64 * 16; i += 256) {
            int row = i >> 4, c4 = (i & 15) << 2;
            int rs = (row & 15) << 1;
            float4 kv = *(const float4*)(kbase + (kt * 64 + row) * HD + c4);
            sKS[row][(c4 + 0) ^ rs] = kv.x;
            sKS[row][(c4 + 1) ^ rs] = kv.y;
            sKS[row][(c4 + 2) ^ rs] = kv.z;
            sKS[row][(c4 + 3) ^ rs] = kv.w;
            *(float4*)&sV[row][c4] = *(const float4*)(vbase + (kt * 64 + row) * HD + c4);
        }
        __syncthreads();

        // scores S = Q K^T
        float sc[4][4];
#pragma unroll
        for (int r = 0; r < 4; r++)
#pragma unroll
            for (int c = 0; c < 4; c++) sc[r][c] = 0.f;

#pragma unroll 4
        for (int d = 0; d < 64; d++) {
            float qv[4];
#pragma unroll
            for (int r = 0; r < 4; r++) qv[r] = sQ[ty + 16 * r][d];
#pragma unroll
            for (int c = 0; c < 4; c++) {
                float kv = sKS[tx + 16 * c][d ^ swz];
#pragma unroll
                for (int r = 0; r < 4; r++)
                    sc[r][c] = fmaf(qv[r], kv, sc[r][c]);
            }
        }

        // scale + mask
#pragma unroll
        for (int c = 0; c < 4; c++) {
            int jg = kt * 64 + tx + 16 * c;
            bool ok = jg < vlen;
#pragma unroll
            for (int r = 0; r < 4; r++)
                sc[r][c] = ok ? sc[r][c] * 0.125f : -1e6f;
        }

        // online softmax (row group = 16 consecutive lanes of one half-warp)
#pragma unroll
        for (int r = 0; r < 4; r++) {
            float tm = fmaxf(fmaxf(sc[r][0], sc[r][1]), fmaxf(sc[r][2], sc[r][3]));
#pragma unroll
            for (int o = 8; o; o >>= 1)
                tm = fmaxf(tm, __shfl_xor_sync(0xffffffffu, tm, o));
            float nm = fmaxf(m_run[r], tm);
            float alpha = __expf(m_run[r] - nm);
            float ts = 0.f;
#pragma unroll
            for (int c = 0; c < 4; c++) {
                float p = __expf(sc[r][c] - nm);
                sc[r][c] = p; ts += p;
            }
#pragma unroll
            for (int o = 8; o; o >>= 1)
                ts += __shfl_xor_sync(0xffffffffu, ts, o);
            m_run[r] = nm;
            l_run[r] = l_run[r] * alpha + ts;
#pragma unroll
            for (int c = 0; c < 4; c++) acc_o[r][c] *= alpha;
        }

        __syncthreads();   // everyone done reading K from sKS

        // stage P into the union buffer (plain layout)
#pragma unroll
        for (int r = 0; r < 4; r++)
#pragma unroll
            for (int c = 0; c < 4; c++)
                sKS[ty + 16 * r][tx + 16 * c] = sc[r][c];
        __syncthreads();

        // O += P @ V
#pragma unroll 4
        for (int j = 0; j < 64; j++) {
            float pv[4], vv[4];
#pragma unroll
            for (int r = 0; r < 4; r++) pv[r] = sKS[ty + 16 * r][j];
#pragma unroll
            for (int c = 0; c < 4; c++) vv[c] = sV[j][tx + 16 * c];
#pragma unroll
            for (int r = 0; r < 4; r++)
#pragma unroll
                for (int c = 0; c < 4; c++)
                    acc_o[r][c] = fmaf(pv[r], vv[c], acc_o[r][c]);
        }
    }

    // finalize: divide by l, write ctx in [B,S,D] layout
#pragma unroll
    for (int r = 0; r < 4; r++) {
        int s = qt * 64 + ty + 16 * r;
        float inv = 1.f / l_run[r];
#pragma unroll
        for (int c = 0; c < 4; c++) {
            int dd = tx + 16 * c;
            g_ctx[(b * SEQ + s) * DIM + h * HD + dd] = acc_o[r][c] * inv;
        }
    }
}

// ---------------------------------------------------------------------------
extern "C" void kernel_launch(void* const* d_in, const int* in_sizes, int n_in,
                              void* d_out, int out_size)
{
    const float* queries = (const float*)d_in[0];
    const float* keys    = (const float*)d_in[1];
    const float* values  = (const float*)d_in[2];
    const int*   vlens   = (const int*)d_in[3];
    const float* W_q     = (const float*)d_in[4];
    const float* W_o     = (const float*)d_in[5];
    float* out = (float*)d_out;

    // 1) Q/K/V projections (all with W_q, per reference)
    proj_kernel<<<dim3(DIM / 128, (BATCH * SEQ) / 128, 3), 256>>>(
        queries, keys, values, W_q);

    // 2) fused masked attention
    attn_kernel<<<dim3(SEQ / 64, NH, BATCH), 256>>>(vlens);

    // 3) output projection
    out_kernel<<<dim3(DIM / 128, (BATCH * SEQ) / 128), 256>>>(W_o, out);
}

// round 3
// speedup vs baseline: 2.3645x; 2.3645x over previous
#include <cuda_runtime.h>
#include <cstdint>

#define BATCH 4
#define SEQ   1024
#define DIM   1024
#define NH    16
#define HD    64

// -------------------- device scratch (allocation-free) ----------------------
__device__ float g_q[BATCH * NH * SEQ * HD];     // proj outputs, head-split
__device__ float g_k[BATCH * NH * SEQ * HD];
__device__ float g_v[BATCH * NH * SEQ * HD];
__device__ float g_ctx[BATCH * SEQ * DIM];       // attn output (tf32-rna rounded)
__device__ float g_qr[BATCH * SEQ * DIM];        // rna-rounded inputs
__device__ float g_kr[BATCH * SEQ * DIM];
__device__ float g_vr[BATCH * SEQ * DIM];
__device__ float g_wqr[DIM * DIM];
__device__ float g_wor[DIM * DIM];

// -------------------- helpers ----------------------------------------------
__device__ __forceinline__ uint32_t smem_u32(const void* p) {
    uint32_t a;
    asm("{ .reg .u64 t; cvta.to.shared.u64 t, %1; cvt.u32.u64 %0, t; }" : "=r"(a) : "l"(p));
    return a;
}
__device__ __forceinline__ float f_rna_tf32(float f) {
    uint32_t r; asm("cvt.rna.tf32.f32 %0, %1;" : "=r"(r) : "f"(f));
    return __uint_as_float(r);
}

#define CP_ASYNC16(sa, gp) \
    asm volatile("cp.async.cg.shared.global [%0], [%1], 16;" :: "r"(sa), "l"(gp))
#define CP_COMMIT() asm volatile("cp.async.commit_group;" ::: "memory")
#define CP_WAIT(n)  asm volatile("cp.async.wait_group %0;" :: "n"(n) : "memory")

__device__ __forceinline__ void mma_tf32(float& d0, float& d1, float& d2, float& d3,
                                         uint32_t a0, uint32_t a1, uint32_t a2, uint32_t a3,
                                         uint32_t b0, uint32_t b1) {
    asm volatile(
        "mma.sync.aligned.m16n8k8.row.col.f32.tf32.tf32.f32 "
        "{%0,%1,%2,%3}, {%4,%5,%6,%7}, {%8,%9}, {%0,%1,%2,%3};"
        : "+f"(d0), "+f"(d1), "+f"(d2), "+f"(d3)
        : "r"(a0), "r"(a1), "r"(a2), "r"(a3), "r"(b0), "r"(b1));
}

// -------------------- prep: rna-round everything once -----------------------
__global__ void prep_rna(const float* __restrict__ q, const float* __restrict__ k,
                         const float* __restrict__ v, const float* __restrict__ wq,
                         const float* __restrict__ wo)
{
    const float* src; float* dst; int n4;
    switch (blockIdx.y) {
        case 0: src = q;  dst = g_qr;  n4 = (BATCH * SEQ * DIM) / 4; break;
        case 1: src = k;  dst = g_kr;  n4 = (BATCH * SEQ * DIM) / 4; break;
        case 2: src = v;  dst = g_vr;  n4 = (BATCH * SEQ * DIM) / 4; break;
        case 3: src = wq; dst = g_wqr; n4 = (DIM * DIM) / 4; break;
        default: src = wo; dst = g_wor; n4 = (DIM * DIM) / 4; break;
    }
    for (int i = blockIdx.x * blockDim.x + threadIdx.x; i < n4; i += gridDim.x * blockDim.x) {
        float4 x = ((const float4*)src)[i];
        x.x = f_rna_tf32(x.x); x.y = f_rna_tf32(x.y);
        x.z = f_rna_tf32(x.z); x.w = f_rna_tf32(x.w);
        ((float4*)dst)[i] = x;
    }
}

// -------------------- tf32 mma.sync GEMM ------------------------------------
// 128x128 tile, BK=32, 256 thr (8 warps, 2x4), warp tile 64x32.
// A smem [m][k] pitch 36 (fragment LDS conflict-free: bank = 4r+k).
// B smem [k][n] pitch 136 (bank = 8k+n).
#define PITCH_A 36
#define PITCH_B 136
#define A_BUF (128 * PITCH_A)               // 4608 floats
#define B_BUF (32 * PITCH_B)                // 4352 floats
#define OFF_A(b) ((b) * A_BUF)
#define OFF_B(b) (2 * A_BUF + (b) * B_BUF)
#define GEMM_SMEM_BYTES ((2 * A_BUF + 2 * B_BUF) * 4)   // 71680
#define KCHUNKS 32

// MODE 0: proj (z: g_qr/g_kr/g_vr @ g_wqr -> g_q/g_k/g_v head-split)
// MODE 1: out  (g_ctx @ g_wor -> outp plain)
template<int MODE>
__global__ __launch_bounds__(256, 2) void gemm_mma(float* __restrict__ outp)
{
    extern __shared__ float sm[];
    const uint32_t sb = smem_u32(sm);
    const int tid = threadIdx.x, lane = tid & 31, wid = tid >> 5;
    const int wm = wid >> 2, wn = wid & 3;           // warp grid 2x4
    const int m0 = blockIdx.y * 128, n0 = blockIdx.x * 128;

    const float* A; const float* B; float* dst;
    if (MODE == 0) {
        int z = blockIdx.z;
        A   = (z == 0) ? g_qr : (z == 1) ? g_kr : g_vr;
        dst = (z == 0) ? g_q  : (z == 1) ? g_k  : g_v;
        B   = g_wqr;
    } else {
        A = g_ctx; dst = outp; B = g_wor;
    }

    // staging addresses (4 x 16B each for A and B per chunk)
    uint32_t saA[4], saB[4];
    const float* gpA[4]; const float* gpB[4];
#pragma unroll
    for (int i = 0; i < 4; i++) {
        int s = tid + i * 256;
        int ar = s >> 3, ac = s & 7;                 // A: row 0..127, 16B col 0..7
        saA[i] = sb + (ar * PITCH_A + ac * 4) * 4;
        gpA[i] = A + (m0 + ar) * DIM + ac * 4;
        int br = s >> 5, bc = s & 31;                // B: row 0..31, 16B col 0..31
        saB[i] = sb + (2 * A_BUF + br * PITCH_B + bc * 4) * 4;
        gpB[i] = B + br * DIM + n0 + bc * 4;
    }

    float acc[4][4][4];
#pragma unroll
    for (int mf = 0; mf < 4; mf++)
#pragma unroll
        for (int nf = 0; nf < 4; nf++)
#pragma unroll
            for (int e = 0; e < 4; e++) acc[mf][nf][e] = 0.f;

    // prologue: stage chunk 0 into buf 0
#pragma unroll
    for (int i = 0; i < 4; i++) CP_ASYNC16(saA[i], gpA[i]);
#pragma unroll
    for (int i = 0; i < 4; i++) CP_ASYNC16(saB[i], gpB[i]);
    CP_COMMIT();

    const int ar = lane >> 2, ac = lane & 3;         // fragment lane decomposition

#pragma unroll 1
    for (int t = 0; t < KCHUNKS; t++) {
        const int buf = t & 1;
        if (t + 1 < KCHUNKS) {
            const int nb = (t + 1) & 1;
            const uint32_t dA = nb * A_BUF * 4, dB = nb * B_BUF * 4;
#pragma unroll
            for (int i = 0; i < 4; i++) CP_ASYNC16(saA[i] + dA, gpA[i] + (t + 1) * 32);
#pragma unroll
            for (int i = 0; i < 4; i++) CP_ASYNC16(saB[i] + dB, gpB[i] + (t + 1) * 32 * DIM);
            CP_COMMIT();
            CP_WAIT(1);
        } else {
            CP_WAIT(0);
        }
        __syncthreads();

        const uint32_t* As = (const uint32_t*)(sm + OFF_A(buf));
        const uint32_t* Bs = (const uint32_t*)(sm + OFF_B(buf));

#pragma unroll
        for (int kk = 0; kk < 32; kk += 8) {
            uint32_t a[4][4], b[4][2];
#pragma unroll
            for (int mf = 0; mf < 4; mf++) {
                int r = (wm * 64 + mf * 16 + ar) * PITCH_A;
                a[mf][0] = As[r + kk + ac];
                a[mf][1] = As[r + 8 * PITCH_A + kk + ac];
                a[mf][2] = As[r + kk + ac + 4];
                a[mf][3] = As[r + 8 * PITCH_A + kk + ac + 4];
            }
#pragma unroll
            for (int nf = 0; nf < 4; nf++) {
                int n = wn * 32 + nf * 8 + ar;
                b[nf][0] = Bs[(kk + ac) * PITCH_B + n];
                b[nf][1] = Bs[(kk + ac + 4) * PITCH_B + n];
            }
#pragma unroll
            for (int mf = 0; mf < 4; mf++)
#pragma unroll
                for (int nf = 0; nf < 4; nf++)
                    mma_tf32(acc[mf][nf][0], acc[mf][nf][1], acc[mf][nf][2], acc[mf][nf][3],
                             a[mf][0], a[mf][1], a[mf][2], a[mf][3],
                             b[nf][0], b[nf][1]);
        }
        __syncthreads();
    }

    // epilogue: direct float2 stores
#pragma unroll
    for (int mf = 0; mf < 4; mf++) {
#pragma unroll
        for (int nf = 0; nf < 4; nf++) {
            int m = m0 + wm * 64 + mf * 16 + ar;
            int n = n0 + wn * 32 + nf * 8 + ac * 2;
            float2 lo = make_float2(acc[mf][nf][0], acc[mf][nf][1]);
            float2 hi = make_float2(acc[mf][nf][2], acc[mf][nf][3]);
            if (MODE == 0) {
                int h = n >> 6, dd = n & 63;
                int bb0 = m >> 10, s0 = m & 1023;
                int bb1 = (m + 8) >> 10, s1 = (m + 8) & 1023;
                *(float2*)&dst[(((bb0 * NH + h) * SEQ) + s0) * HD + dd] = lo;
                *(float2*)&dst[(((bb1 * NH + h) * SEQ) + s1) * HD + dd] = hi;
            } else {
                *(float2*)&dst[m * DIM + n] = lo;
                *(float2*)&dst[(m + 8) * DIM + n] = hi;
            }
        }
    }
}

// -------------------- fused SIMT flash attention ----------------------------
__global__ __launch_bounds__(256) void attn_kernel(const int* __restrict__ vlens)
{
    const int qt = blockIdx.x, h = blockIdx.y, b = blockIdx.z;
    const int vlen = vlens[b];

    __shared__ float sQ[64][64];
    __shared__ float sKS[64][64];
    __shared__ float sV[64][64];

    const int tid = threadIdx.x;
    const int tx = tid & 15, ty = tid >> 4;

    const float* qbase = g_q + ((b * NH + h) * SEQ + qt * 64) * HD;
    const float* kbase = g_k + ((b * NH + h) * SEQ) * HD;
    const float* vbase = g_v + ((b * NH + h) * SEQ) * HD;

    for (int i = tid; i < 64 * 16; i += 256) {
        int row = i >> 4, c4 = (i & 15) << 2;
        *(float4*)&sQ[row][c4] = *(const float4*)(qbase + row * HD + c4);
    }

    float m_run[4], l_run[4], acc_o[4][4];
#pragma unroll
    for (int r = 0; r < 4; r++) {
        m_run[r] = -1e30f; l_run[r] = 0.f;
#pragma unroll
        for (int c = 0; c < 4; c++) acc_o[r][c] = 0.f;
    }

    const int ntiles = (vlen + 63) >> 6;
    const int swz = tx << 1;

    for (int kt = 0; kt < ntiles; kt++) {
        __syncthreads();
        for (int i = tid; i < 64 * 16; i += 256) {
            int row = i >> 4, c4 = (i & 15) << 2;
            int rs = (row & 15) << 1;
            float4 kv = *(const float4*)(kbase + (kt * 64 + row) * HD + c4);
            sKS[row][(c4 + 0) ^ rs] = kv.x;
            sKS[row][(c4 + 1) ^ rs] = kv.y;
            sKS[row][(c4 + 2) ^ rs] = kv.z;
            sKS[row][(c4 + 3) ^ rs] = kv.w;
            *(float4*)&sV[row][c4] = *(const float4*)(vbase + (kt * 64 + row) * HD + c4);
        }
        __syncthreads();

        float sc[4][4];
#pragma unroll
        for (int r = 0; r < 4; r++)
#pragma unroll
            for (int c = 0; c < 4; c++) sc[r][c] = 0.f;

#pragma unroll 4
        for (int d = 0; d < 64; d++) {
            float qv[4];
#pragma unroll
            for (int r = 0; r < 4; r++) qv[r] = sQ[ty + 16 * r][d];
#pragma unroll
            for (int c = 0; c < 4; c++) {
                float kv = sKS[tx + 16 * c][d ^ swz];
#pragma unroll
                for (int r = 0; r < 4; r++)
                    sc[r][c] = fmaf(qv[r], kv, sc[r][c]);
            }
        }

#pragma unroll
        for (int c = 0; c < 4; c++) {
            int jg = kt * 64 + tx + 16 * c;
            bool ok = jg < vlen;
#pragma unroll
            for (int r = 0; r < 4; r++)
                sc[r][c] = ok ? sc[r][c] * 0.125f : -1e6f;
        }

#pragma unroll
        for (int r = 0; r < 4; r++) {
            float tm = fmaxf(fmaxf(sc[r][0], sc[r][1]), fmaxf(sc[r][2], sc[r][3]));
#pragma unroll
            for (int o = 8; o; o >>= 1)
                tm = fmaxf(tm, __shfl_xor_sync(0xffffffffu, tm, o));
            float nm = fmaxf(m_run[r], tm);
            float alpha = __expf(m_run[r] - nm);
            float ts = 0.f;
#pragma unroll
            for (int c = 0; c < 4; c++) {
                float p = __expf(sc[r][c] - nm);
                sc[r][c] = p; ts += p;
            }
#pragma unroll
            for (int o = 8; o; o >>= 1)
                ts += __shfl_xor_sync(0xffffffffu, ts, o);
            m_run[r] = nm;
            l_run[r] = l_run[r] * alpha + ts;
#pragma unroll
            for (int c = 0; c < 4; c++) acc_o[r][c] *= alpha;
        }

        __syncthreads();
#pragma unroll
        for (int r = 0; r < 4; r++)
#pragma unroll
            for (int c = 0; c < 4; c++)
                sKS[ty + 16 * r][tx + 16 * c] = sc[r][c];
        __syncthreads();

#pragma unroll 4
        for (int j = 0; j < 64; j++) {
            float pv[4], vv[4];
#pragma unroll
            for (int r = 0; r < 4; r++) pv[r] = sKS[ty + 16 * r][j];
#pragma unroll
            for (int c = 0; c < 4; c++) vv[c] = sV[j][tx + 16 * c];
#pragma unroll
            for (int r = 0; r < 4; r++)
#pragma unroll
                for (int c = 0; c < 4; c++)
                    acc_o[r][c] = fmaf(pv[r], vv[c], acc_o[r][c]);
        }
    }

    // finalize + tf32-rna round so the output GEMM needs no per-tile cvt
#pragma unroll
    for (int r = 0; r < 4; r++) {
        int s = qt * 64 + ty + 16 * r;
        float inv = 1.f / l_run[r];
#pragma unroll
        for (int c = 0; c < 4; c++) {
            int dd = tx + 16 * c;
            g_ctx[(b * SEQ + s) * DIM + h * HD + dd] = f_rna_tf32(acc_o[r][c] * inv);
        }
    }
}

// ---------------------------------------------------------------------------
extern "C" void kernel_launch(void* const* d_in, const int* in_sizes, int n_in,
                              void* d_out, int out_size)
{
    const float* queries = (const float*)d_in[0];
    const float* keys    = (const float*)d_in[1];
    const float* values  = (const float*)d_in[2];
    const int*   vlens   = (const int*)d_in[3];
    const float* W_q     = (const float*)d_in[4];
    const float* W_o     = (const float*)d_in[5];
    float* out = (float*)d_out;

    cudaFuncSetAttribute(gemm_mma<0>, cudaFuncAttributeMaxDynamicSharedMemorySize, GEMM_SMEM_BYTES);
    cudaFuncSetAttribute(gemm_mma<1>, cudaFuncAttributeMaxDynamicSharedMemorySize, GEMM_SMEM_BYTES);

    prep_rna<<<dim3(512, 5), 256>>>(queries, keys, values, W_q, W_o);
    gemm_mma<0><<<dim3(8, 32, 3), 256, GEMM_SMEM_BYTES>>>(nullptr);
    attn_kernel<<<dim3(SEQ / 64, NH, BATCH), 256>>>(vlens);
    gemm_mma<1><<<dim3(8, 32, 1), 256, GEMM_SMEM_BYTES>>>(out);
}

// round 4
// speedup vs baseline: 3.2443x; 1.3721x over previous
#include <cuda_runtime.h>
#include <cstdint>

#define BATCH 4
#define SEQ   1024
#define DIM   1024
#define NH    16
#define HD    64

// -------------------- device scratch (allocation-free) ----------------------
__device__ float g_q[BATCH * NH * SEQ * HD];     // proj outputs, head-split, tf32-rounded
__device__ float g_k[BATCH * NH * SEQ * HD];
__device__ float g_v[BATCH * NH * SEQ * HD];
__device__ float g_vt[BATCH * NH * HD * SEQ];    // V transposed [b,h,d,s]
__device__ float g_ctx[BATCH * SEQ * DIM];       // attn output (tf32-rna rounded)
__device__ float g_qr[BATCH * SEQ * DIM];        // rna-rounded inputs
__device__ float g_kr[BATCH * SEQ * DIM];
__device__ float g_vr[BATCH * SEQ * DIM];
__device__ float g_wqr[DIM * DIM];
__device__ float g_wor[DIM * DIM];

// -------------------- helpers ----------------------------------------------
__device__ __forceinline__ uint32_t smem_u32(const void* p) {
    uint32_t a;
    asm("{ .reg .u64 t; cvta.to.shared.u64 t, %1; cvt.u32.u64 %0, t; }" : "=r"(a) : "l"(p));
    return a;
}
__device__ __forceinline__ float f_rna_tf32(float f) {
    uint32_t r; asm("cvt.rna.tf32.f32 %0, %1;" : "=r"(r) : "f"(f));
    return __uint_as_float(r);
}

#define CP_ASYNC16(sa, gp) \
    asm volatile("cp.async.cg.shared.global [%0], [%1], 16;" :: "r"(sa), "l"(gp))
#define CP_COMMIT() asm volatile("cp.async.commit_group;" ::: "memory")
#define CP_WAIT(n)  asm volatile("cp.async.wait_group %0;" :: "n"(n) : "memory")

__device__ __forceinline__ void mma_tf32(float& d0, float& d1, float& d2, float& d3,
                                         uint32_t a0, uint32_t a1, uint32_t a2, uint32_t a3,
                                         uint32_t b0, uint32_t b1) {
    asm volatile(
        "mma.sync.aligned.m16n8k8.row.col.f32.tf32.tf32.f32 "
        "{%0,%1,%2,%3}, {%4,%5,%6,%7}, {%8,%9}, {%0,%1,%2,%3};"
        : "+f"(d0), "+f"(d1), "+f"(d2), "+f"(d3)
        : "r"(a0), "r"(a1), "r"(a2), "r"(a3), "r"(b0), "r"(b1));
}

// -------------------- prep: rna-round inputs + weights ----------------------
__global__ void prep_rna(const float* __restrict__ q, const float* __restrict__ k,
                         const float* __restrict__ v, const float* __restrict__ wq,
                         const float* __restrict__ wo)
{
    const float* src; float* dst; int n4;
    switch (blockIdx.y) {
        case 0: src = q;  dst = g_qr;  n4 = (BATCH * SEQ * DIM) / 4; break;
        case 1: src = k;  dst = g_kr;  n4 = (BATCH * SEQ * DIM) / 4; break;
        case 2: src = v;  dst = g_vr;  n4 = (BATCH * SEQ * DIM) / 4; break;
        case 3: src = wq; dst = g_wqr; n4 = (DIM * DIM) / 4; break;
        default: src = wo; dst = g_wor; n4 = (DIM * DIM) / 4; break;
    }
    for (int i = blockIdx.x * blockDim.x + threadIdx.x; i < n4; i += gridDim.x * blockDim.x) {
        float4 x = ((const float4*)src)[i];
        x.x = f_rna_tf32(x.x); x.y = f_rna_tf32(x.y);
        x.z = f_rna_tf32(x.z); x.w = f_rna_tf32(x.w);
        ((float4*)dst)[i] = x;
    }
}

// -------------------- V transpose: [bh,s,d] -> [bh,d,s] ---------------------
__global__ void transpose_v()
{
    __shared__ float t[32][33];
    const int tid = threadIdx.x;
    const int s0 = blockIdx.x * 32, d0 = blockIdx.y * 32, z = blockIdx.z;
    const float* src = g_v + (size_t)z * SEQ * HD;
    float* dst = g_vt + (size_t)z * HD * SEQ;
#pragma unroll
    for (int i = 0; i < 4; i++) {
        int idx = tid + i * 256, r = idx >> 5, c = idx & 31;
        t[r][c] = src[(s0 + r) * HD + d0 + c];
    }
    __syncthreads();
#pragma unroll
    for (int i = 0; i < 4; i++) {
        int idx = tid + i * 256, r = idx >> 5, c = idx & 31;   // r = d, c = s
        dst[(d0 + r) * SEQ + s0 + c] = t[c][r];
    }
}

// -------------------- tf32 mma.sync GEMM (3-stage pipeline) -----------------
#define PITCH_A 36
#define PITCH_B 136
#define A_BUF (128 * PITCH_A)               // 4608 floats
#define B_BUF (32 * PITCH_B)                // 4352 floats
#define OFF_A(b) ((b) * A_BUF)
#define OFF_B(b) (3 * A_BUF + (b) * B_BUF)
#define GEMM_SMEM_BYTES ((3 * A_BUF + 3 * B_BUF) * 4)   // 107520
#define KCHUNKS 32

// MODE 0: proj (z: g_qr/g_kr/g_vr @ g_wqr -> g_q/g_k/g_v head-split, rounded)
// MODE 1: out  (g_ctx @ g_wor -> outp plain)
template<int MODE>
__global__ __launch_bounds__(256, 2) void gemm_mma(float* __restrict__ outp)
{
    extern __shared__ float sm[];
    const uint32_t sb = smem_u32(sm);
    const int tid = threadIdx.x, lane = tid & 31, wid = tid >> 5;
    const int wm = wid >> 2, wn = wid & 3;           // warp grid 2x4
    const int m0 = blockIdx.y * 128, n0 = blockIdx.x * 128;

    const float* A; const float* B; float* dst;
    if (MODE == 0) {
        int z = blockIdx.z;
        A   = (z == 0) ? g_qr : (z == 1) ? g_kr : g_vr;
        dst = (z == 0) ? g_q  : (z == 1) ? g_k  : g_v;
        B   = g_wqr;
    } else {
        A = g_ctx; dst = outp; B = g_wor;
    }

    uint32_t saA[4], saB[4];
    const float* gpA[4]; const float* gpB[4];
#pragma unroll
    for (int i = 0; i < 4; i++) {
        int s = tid + i * 256;
        int ar = s >> 3, ac = s & 7;
        saA[i] = sb + (ar * PITCH_A + ac * 4) * 4;
        gpA[i] = A + (m0 + ar) * DIM + ac * 4;
        int br = s >> 5, bc = s & 31;
        saB[i] = sb + (3 * A_BUF + br * PITCH_B + bc * 4) * 4;
        gpB[i] = B + br * DIM + n0 + bc * 4;
    }

    float acc[4][4][4];
#pragma unroll
    for (int mf = 0; mf < 4; mf++)
#pragma unroll
        for (int nf = 0; nf < 4; nf++)
#pragma unroll
            for (int e = 0; e < 4; e++) acc[mf][nf][e] = 0.f;

    // prologue: stage chunks 0,1
#pragma unroll
    for (int i = 0; i < 4; i++) CP_ASYNC16(saA[i], gpA[i]);
#pragma unroll
    for (int i = 0; i < 4; i++) CP_ASYNC16(saB[i], gpB[i]);
    CP_COMMIT();
#pragma unroll
    for (int i = 0; i < 4; i++) CP_ASYNC16(saA[i] + A_BUF * 4, gpA[i] + 32);
#pragma unroll
    for (int i = 0; i < 4; i++) CP_ASYNC16(saB[i] + B_BUF * 4, gpB[i] + 32 * DIM);
    CP_COMMIT();

    const int ar = lane >> 2, ac = lane & 3;

#pragma unroll 1
    for (int t = 0; t < KCHUNKS; t++) {
        const int buf = t % 3;
        if (t + 2 < KCHUNKS) {
            const int nb = (t + 2) % 3;
            const uint32_t dA = nb * A_BUF * 4, dB = nb * B_BUF * 4;
#pragma unroll
            for (int i = 0; i < 4; i++) CP_ASYNC16(saA[i] + dA, gpA[i] + (t + 2) * 32);
#pragma unroll
            for (int i = 0; i < 4; i++) CP_ASYNC16(saB[i] + dB, gpB[i] + (t + 2) * 32 * DIM);
            CP_COMMIT();
            CP_WAIT(2);
        } else if (t + 1 < KCHUNKS) {
            CP_WAIT(1);
        } else {
            CP_WAIT(0);
        }
        __syncthreads();

        const uint32_t* As = (const uint32_t*)(sm + OFF_A(buf));
        const uint32_t* Bs = (const uint32_t*)(sm + OFF_B(buf));

#pragma unroll
        for (int kk = 0; kk < 32; kk += 8) {
            uint32_t a[4][4], b[4][2];
#pragma unroll
            for (int mf = 0; mf < 4; mf++) {
                int r = (wm * 64 + mf * 16 + ar) * PITCH_A;
                a[mf][0] = As[r + kk + ac];
                a[mf][1] = As[r + 8 * PITCH_A + kk + ac];
                a[mf][2] = As[r + kk + ac + 4];
                a[mf][3] = As[r + 8 * PITCH_A + kk + ac + 4];
            }
#pragma unroll
            for (int nf = 0; nf < 4; nf++) {
                int n = wn * 32 + nf * 8 + ar;
                b[nf][0] = Bs[(kk + ac) * PITCH_B + n];
                b[nf][1] = Bs[(kk + ac + 4) * PITCH_B + n];
            }
#pragma unroll
            for (int mf = 0; mf < 4; mf++)
#pragma unroll
                for (int nf = 0; nf < 4; nf++)
                    mma_tf32(acc[mf][nf][0], acc[mf][nf][1], acc[mf][nf][2], acc[mf][nf][3],
                             a[mf][0], a[mf][1], a[mf][2], a[mf][3],
                             b[nf][0], b[nf][1]);
        }
        __syncthreads();
    }

    // epilogue
#pragma unroll
    for (int mf = 0; mf < 4; mf++) {
#pragma unroll
        for (int nf = 0; nf < 4; nf++) {
            int m = m0 + wm * 64 + mf * 16 + ar;
            int n = n0 + wn * 32 + nf * 8 + ac * 2;
            if (MODE == 0) {
                // rounded to tf32: these feed tensor-core attention
                float2 lo = make_float2(f_rna_tf32(acc[mf][nf][0]), f_rna_tf32(acc[mf][nf][1]));
                float2 hi = make_float2(f_rna_tf32(acc[mf][nf][2]), f_rna_tf32(acc[mf][nf][3]));
                int h = n >> 6, dd = n & 63;
                int bb0 = m >> 10, s0 = m & 1023;
                int bb1 = (m + 8) >> 10, s1 = (m + 8) & 1023;
                *(float2*)&dst[(((bb0 * NH + h) * SEQ) + s0) * HD + dd] = lo;
                *(float2*)&dst[(((bb1 * NH + h) * SEQ) + s1) * HD + dd] = hi;
            } else {
                float2 lo = make_float2(acc[mf][nf][0], acc[mf][nf][1]);
                float2 hi = make_float2(acc[mf][nf][2], acc[mf][nf][3]);
                *(float2*)&dst[m * DIM + n] = lo;
                *(float2*)&dst[(m + 8) * DIM + n] = hi;
            }
        }
    }
}

// -------------------- tensor-core flash attention ---------------------------
// Block = (qtile 64, h, b), 128 threads = 4 warps, warp owns 16 q-rows.
// S = Q K^T native row.col (A=Q [q][d], B=K [k][d]).
// PV uses g_vt: B = V^T [d][s] native. P: acc-frag -> A-frag via quad shfls.
// Smem (floats, pitch 68): sQ[4352] | sK[2][4352] | sVt[2][4352]  = 87040 B.
#define AP 68
#define ATTN_K0 4352
#define ATTN_V0 (4352 * 3)
#define ATTN_SMEM_BYTES (4352 * 5 * 4)

__global__ __launch_bounds__(128) void attn_tc(const int* __restrict__ vlens)
{
    extern __shared__ float sm[];
    const uint32_t sb = smem_u32(sm);
    const int tid = threadIdx.x, lane = tid & 31, wq = tid >> 5;
    const int qt = blockIdx.x, h = blockIdx.y, b = blockIdx.z;
    const int vlen = vlens[b];
    const int ntiles = (vlen + 63) >> 6;

    const float* qb  = g_q  + ((size_t)(b * NH + h) * SEQ + qt * 64) * HD;
    const float* kb  = g_k  + ((size_t)(b * NH + h) * SEQ) * HD;
    const float* vtb = g_vt + ((size_t)(b * NH + h) * HD) * SEQ;

    // stage Q (group 1 together with K0/V0)
#pragma unroll
    for (int i = 0; i < 8; i++) {
        int idx = tid + i * 128, r = idx >> 4, c4 = (idx & 15) * 4;
        CP_ASYNC16(sb + (r * AP + c4) * 4, qb + r * HD + c4);
    }
    // stage K0 / Vt0 into buffer 0
#pragma unroll
    for (int i = 0; i < 8; i++) {
        int idx = tid + i * 128, r = idx >> 4, c4 = (idx & 15) * 4;
        CP_ASYNC16(sb + (ATTN_K0 + r * AP + c4) * 4, kb + r * HD + c4);
        CP_ASYNC16(sb + (ATTN_V0 + r * AP + c4) * 4, vtb + r * SEQ + c4);
    }
    CP_COMMIT();

    float m_run[2] = {-1e30f, -1e30f};
    float l_run[2] = {0.f, 0.f};
    float oAcc[8][4];
#pragma unroll
    for (int nf = 0; nf < 8; nf++)
#pragma unroll
        for (int e = 0; e < 4; e++) oAcc[nf][e] = 0.f;

    const int lr = lane >> 2, lc = lane & 3;    // fragment row / col lane decomposition
    const int qrow = wq * 16 + lr;

#pragma unroll 1
    for (int kt = 0; kt < ntiles; kt++) {
        if (kt + 1 < ntiles) {
            const int nb = (kt + 1) & 1;
#pragma unroll
            for (int i = 0; i < 8; i++) {
                int idx = tid + i * 128, r = idx >> 4, c4 = (idx & 15) * 4;
                CP_ASYNC16(sb + (ATTN_K0 + nb * 4352 + r * AP + c4) * 4,
                           kb + ((kt + 1) * 64 + r) * HD + c4);
                CP_ASYNC16(sb + (ATTN_V0 + nb * 4352 + r * AP + c4) * 4,
                           vtb + r * SEQ + (kt + 1) * 64 + c4);
            }
            CP_COMMIT();
            CP_WAIT(1);
        } else {
            CP_WAIT(0);
        }
        __syncthreads();

        const uint32_t* Qs = (const uint32_t*)sm;
        const uint32_t* Ks = (const uint32_t*)(sm + ATTN_K0 + (kt & 1) * 4352);
        const uint32_t* Vs = (const uint32_t*)(sm + ATTN_V0 + (kt & 1) * 4352);

        // ---- S = Q K^T ----
        float sAcc[8][4];
#pragma unroll
        for (int nf = 0; nf < 8; nf++)
#pragma unroll
            for (int e = 0; e < 4; e++) sAcc[nf][e] = 0.f;

#pragma unroll
        for (int kk = 0; kk < 64; kk += 8) {
            uint32_t a0 = Qs[qrow * AP + kk + lc];
            uint32_t a1 = Qs[(qrow + 8) * AP + kk + lc];
            uint32_t a2 = Qs[qrow * AP + kk + lc + 4];
            uint32_t a3 = Qs[(qrow + 8) * AP + kk + lc + 4];
#pragma unroll
            for (int nf = 0; nf < 8; nf++) {
                int n = nf * 8 + lr;
                uint32_t b0 = Ks[n * AP + kk + lc];
                uint32_t b1 = Ks[n * AP + kk + lc + 4];
                mma_tf32(sAcc[nf][0], sAcc[nf][1], sAcc[nf][2], sAcc[nf][3],
                         a0, a1, a2, a3, b0, b1);
            }
        }

        // ---- mask + scale + fragment softmax ----
        float rmax0 = -1e30f, rmax1 = -1e30f;
#pragma unroll
        for (int nf = 0; nf < 8; nf++) {
#pragma unroll
            for (int e = 0; e < 2; e++) {
                int col = kt * 64 + nf * 8 + 2 * lc + e;
                bool ok = col < vlen;
                sAcc[nf][e]     = ok ? sAcc[nf][e] * 0.125f     : -1e6f;
                sAcc[nf][2 + e] = ok ? sAcc[nf][2 + e] * 0.125f : -1e6f;
                rmax0 = fmaxf(rmax0, sAcc[nf][e]);
                rmax1 = fmaxf(rmax1, sAcc[nf][2 + e]);
            }
        }
        rmax0 = fmaxf(rmax0, __shfl_xor_sync(0xffffffffu, rmax0, 1));
        rmax0 = fmaxf(rmax0, __shfl_xor_sync(0xffffffffu, rmax0, 2));
        rmax1 = fmaxf(rmax1, __shfl_xor_sync(0xffffffffu, rmax1, 1));
        rmax1 = fmaxf(rmax1, __shfl_xor_sync(0xffffffffu, rmax1, 2));

        float nm0 = fmaxf(m_run[0], rmax0), nm1 = fmaxf(m_run[1], rmax1);
        float alpha0 = __expf(m_run[0] - nm0), alpha1 = __expf(m_run[1] - nm1);
        m_run[0] = nm0; m_run[1] = nm1;

        float ts0 = 0.f, ts1 = 0.f;
#pragma unroll
        for (int nf = 0; nf < 8; nf++) {
#pragma unroll
            for (int e = 0; e < 2; e++) {
                float p0 = f_rna_tf32(__expf(sAcc[nf][e] - nm0));
                float p1 = f_rna_tf32(__expf(sAcc[nf][2 + e] - nm1));
                ts0 += p0; ts1 += p1;
                sAcc[nf][e] = p0; sAcc[nf][2 + e] = p1;
            }
        }
        ts0 += __shfl_xor_sync(0xffffffffu, ts0, 1);
        ts0 += __shfl_xor_sync(0xffffffffu, ts0, 2);
        ts1 += __shfl_xor_sync(0xffffffffu, ts1, 1);
        ts1 += __shfl_xor_sync(0xffffffffu, ts1, 2);
        l_run[0] = l_run[0] * alpha0 + ts0;
        l_run[1] = l_run[1] * alpha1 + ts1;

#pragma unroll
        for (int nf = 0; nf < 8; nf++) {
            oAcc[nf][0] *= alpha0; oAcc[nf][1] *= alpha0;
            oAcc[nf][2] *= alpha1; oAcc[nf][3] *= alpha1;
        }

        // ---- O += P V : P acc-frag -> A-frag via quad shfl ----
        const int srcA = (lane & ~3) | (lc >> 1);
        const int srcB = srcA + 2;
        const bool oddc = lc & 1;
#pragma unroll
        for (int kc = 0; kc < 8; kc++) {
            float v0 = __shfl_sync(0xffffffffu, sAcc[kc][0], srcA);
            float v1 = __shfl_sync(0xffffffffu, sAcc[kc][1], srcA);
            float v2 = __shfl_sync(0xffffffffu, sAcc[kc][2], srcA);
            float v3 = __shfl_sync(0xffffffffu, sAcc[kc][3], srcA);
            float u0 = __shfl_sync(0xffffffffu, sAcc[kc][0], srcB);
            float u1 = __shfl_sync(0xffffffffu, sAcc[kc][1], srcB);
            float u2 = __shfl_sync(0xffffffffu, sAcc[kc][2], srcB);
            float u3 = __shfl_sync(0xffffffffu, sAcc[kc][3], srcB);
            uint32_t a0 = __float_as_uint(oddc ? v1 : v0);
            uint32_t a1 = __float_as_uint(oddc ? v3 : v2);
            uint32_t a2 = __float_as_uint(oddc ? u1 : u0);
            uint32_t a3 = __float_as_uint(oddc ? u3 : u2);
#pragma unroll
            for (int nf = 0; nf < 8; nf++) {
                int n = nf * 8 + lr;                 // output dim
                uint32_t b0 = Vs[n * AP + kc * 8 + lc];
                uint32_t b1 = Vs[n * AP + kc * 8 + lc + 4];
                mma_tf32(oAcc[nf][0], oAcc[nf][1], oAcc[nf][2], oAcc[nf][3],
                         a0, a1, a2, a3, b0, b1);
            }
        }
        __syncthreads();   // before next-tile staging overwrites buffers
    }

    // ---- epilogue: normalize, round, store ctx ----
    float inv0 = 1.f / l_run[0], inv1 = 1.f / l_run[1];
    int row0 = qt * 64 + wq * 16 + lr;
    int row1 = row0 + 8;
#pragma unroll
    for (int nf = 0; nf < 8; nf++) {
        int col = h * HD + nf * 8 + 2 * lc;
        float2 lo = make_float2(f_rna_tf32(oAcc[nf][0] * inv0), f_rna_tf32(oAcc[nf][1] * inv0));
        float2 hi = make_float2(f_rna_tf32(oAcc[nf][2] * inv1), f_rna_tf32(oAcc[nf][3] * inv1));
        *(float2*)&g_ctx[(b * SEQ + row0) * DIM + col] = lo;
        *(float2*)&g_ctx[(b * SEQ + row1) * DIM + col] = hi;
    }
}

// ---------------------------------------------------------------------------
extern "C" void kernel_launch(void* const* d_in, const int* in_sizes, int n_in,
                              void* d_out, int out_size)
{
    const float* queries = (const float*)d_in[0];
    const float* keys    = (const float*)d_in[1];
    const float* values  = (const float*)d_in[2];
    const int*   vlens   = (const int*)d_in[3];
    const float* W_q     = (const float*)d_in[4];
    const float* W_o     = (const float*)d_in[5];
    float* out = (float*)d_out;

    cudaFuncSetAttribute(gemm_mma<0>, cudaFuncAttributeMaxDynamicSharedMemorySize, GEMM_SMEM_BYTES);
    cudaFuncSetAttribute(gemm_mma<1>, cudaFuncAttributeMaxDynamicSharedMemorySize, GEMM_SMEM_BYTES);
    cudaFuncSetAttribute(attn_tc, cudaFuncAttributeMaxDynamicSharedMemorySize, ATTN_SMEM_BYTES);

    prep_rna<<<dim3(512, 5), 256>>>(queries, keys, values, W_q, W_o);
    gemm_mma<0><<<dim3(8, 32, 3), 256, GEMM_SMEM_BYTES>>>(nullptr);
    transpose_v<<<dim3(SEQ / 32, HD / 32, BATCH * NH), 256>>>();
    attn_tc<<<dim3(SEQ / 64, NH, BATCH), 128, ATTN_SMEM_BYTES>>>(vlens);
    gemm_mma<1><<<dim3(8, 32, 1), 256, GEMM_SMEM_BYTES>>>(out);
}

// round 5
// speedup vs baseline: 3.9912x; 1.2302x over previous
#include <cuda_runtime.h>
#include <cstdint>

#define BATCH 4
#define SEQ   1024
#define DIM   1024
#define NH    16
#define HD    64

// -------------------- device scratch (allocation-free) ----------------------
__device__ float g_q[BATCH * NH * SEQ * HD];     // proj outputs, head-split, tf32-rounded
__device__ float g_k[BATCH * NH * SEQ * HD];
__device__ float g_v[BATCH * NH * SEQ * HD];
__device__ float g_vt[BATCH * NH * HD * SEQ];    // V transposed [b,h,d,s]
__device__ float g_ctx[BATCH * SEQ * DIM];       // attn output (tf32-rna rounded)
__device__ float g_qr[BATCH * SEQ * DIM];        // rna-rounded inputs
__device__ float g_kr[BATCH * SEQ * DIM];
__device__ float g_vr[BATCH * SEQ * DIM];
__device__ float g_wqr[DIM * DIM];
__device__ float g_wor[DIM * DIM];

// -------------------- helpers ----------------------------------------------
__device__ __forceinline__ uint32_t smem_u32(const void* p) {
    uint32_t a;
    asm("{ .reg .u64 t; cvta.to.shared.u64 t, %1; cvt.u32.u64 %0, t; }" : "=r"(a) : "l"(p));
    return a;
}
__device__ __forceinline__ float f_rna_tf32(float f) {
    uint32_t r; asm("cvt.rna.tf32.f32 %0, %1;" : "=r"(r) : "f"(f));
    return __uint_as_float(r);
}

#define CP_ASYNC16(sa, gp) \
    asm volatile("cp.async.cg.shared.global [%0], [%1], 16;" :: "r"(sa), "l"(gp))
#define CP_COMMIT() asm volatile("cp.async.commit_group;" ::: "memory")
#define CP_WAIT(n)  asm volatile("cp.async.wait_group %0;" :: "n"(n) : "memory")

__device__ __forceinline__ void mma_tf32(float& d0, float& d1, float& d2, float& d3,
                                         uint32_t a0, uint32_t a1, uint32_t a2, uint32_t a3,
                                         uint32_t b0, uint32_t b1) {
    asm volatile(
        "mma.sync.aligned.m16n8k8.row.col.f32.tf32.tf32.f32 "
        "{%0,%1,%2,%3}, {%4,%5,%6,%7}, {%8,%9}, {%0,%1,%2,%3};"
        : "+f"(d0), "+f"(d1), "+f"(d2), "+f"(d3)
        : "r"(a0), "r"(a1), "r"(a2), "r"(a3), "r"(b0), "r"(b1));
}

// -------------------- prep: rna-round inputs + weights ----------------------
__global__ void prep_rna(const float* __restrict__ q, const float* __restrict__ k,
                         const float* __restrict__ v, const float* __restrict__ wq,
                         const float* __restrict__ wo)
{
    const float* src; float* dst; int n4;
    switch (blockIdx.y) {
        case 0: src = q;  dst = g_qr;  n4 = (BATCH * SEQ * DIM) / 4; break;
        case 1: src = k;  dst = g_kr;  n4 = (BATCH * SEQ * DIM) / 4; break;
        case 2: src = v;  dst = g_vr;  n4 = (BATCH * SEQ * DIM) / 4; break;
        case 3: src = wq; dst = g_wqr; n4 = (DIM * DIM) / 4; break;
        default: src = wo; dst = g_wor; n4 = (DIM * DIM) / 4; break;
    }
    for (int i = blockIdx.x * blockDim.x + threadIdx.x; i < n4; i += gridDim.x * blockDim.x) {
        float4 x = ((const float4*)src)[i];
        x.x = f_rna_tf32(x.x); x.y = f_rna_tf32(x.y);
        x.z = f_rna_tf32(x.z); x.w = f_rna_tf32(x.w);
        ((float4*)dst)[i] = x;
    }
}

// -------------------- V transpose: [bh,s,d] -> [bh,d,s] (vlen-skipped) ------
__global__ void transpose_v(const int* __restrict__ vlens)
{
    __shared__ float t[32][33];
    const int tid = threadIdx.x;
    const int s0 = blockIdx.x * 32, d0 = blockIdx.y * 32, z = blockIdx.z;
    if (s0 >= vlens[z / NH]) return;     // masked rows never read through live P
    const float* src = g_v + (size_t)z * SEQ * HD;
    float* dst = g_vt + (size_t)z * HD * SEQ;
#pragma unroll
    for (int i = 0; i < 4; i++) {
        int idx = tid + i * 256, r = idx >> 5, c = idx & 31;
        t[r][c] = src[(s0 + r) * HD + d0 + c];
    }
    __syncthreads();
#pragma unroll
    for (int i = 0; i < 4; i++) {
        int idx = tid + i * 256, r = idx >> 5, c = idx & 31;   // r = d, c = s
        dst[(d0 + r) * SEQ + s0 + c] = t[c][r];
    }
}

// -------------------- tf32 mma.sync GEMM (3-stage pipeline) -----------------
#define PITCH_A 36
#define PITCH_B 136
#define A_BUF (128 * PITCH_A)               // 4608 floats
#define B_BUF (32 * PITCH_B)                // 4352 floats
#define OFF_A(b) ((b) * A_BUF)
#define OFF_B(b) (3 * A_BUF + (b) * B_BUF)
#define GEMM_SMEM_BYTES ((3 * A_BUF + 3 * B_BUF) * 4)   // 107520
#define KCHUNKS 32

// MODE 0: proj (z: g_qr/g_kr/g_vr @ g_wqr -> g_q/g_k/g_v head-split, rounded)
//         K/V blocks fully past valid_length early-exit.
// MODE 1: out  (g_ctx @ g_wor -> outp plain)
template<int MODE>
__global__ __launch_bounds__(256, 2) void gemm_mma(float* __restrict__ outp,
                                                   const int* __restrict__ vlens)
{
    extern __shared__ float sm[];
    const uint32_t sb = smem_u32(sm);
    const int tid = threadIdx.x, lane = tid & 31, wid = tid >> 5;
    const int wm = wid >> 2, wn = wid & 3;           // warp grid 2x4
    const int m0 = blockIdx.y * 128, n0 = blockIdx.x * 128;

    const float* A; const float* B; float* dst;
    if (MODE == 0) {
        int z = blockIdx.z;
        A   = (z == 0) ? g_qr : (z == 1) ? g_kr : g_vr;
        dst = (z == 0) ? g_q  : (z == 1) ? g_k  : g_v;
        B   = g_wqr;
        // skip K/V projection blocks entirely past this batch's valid length
        if (z != 0 && (m0 & 1023) >= vlens[m0 >> 10]) return;
    } else {
        A = g_ctx; dst = outp; B = g_wor;
    }

    uint32_t saA[4], saB[4];
    const float* gpA[4]; const float* gpB[4];
#pragma unroll
    for (int i = 0; i < 4; i++) {
        int s = tid + i * 256;
        int ar = s >> 3, ac = s & 7;
        saA[i] = sb + (ar * PITCH_A + ac * 4) * 4;
        gpA[i] = A + (m0 + ar) * DIM + ac * 4;
        int br = s >> 5, bc = s & 31;
        saB[i] = sb + (3 * A_BUF + br * PITCH_B + bc * 4) * 4;
        gpB[i] = B + br * DIM + n0 + bc * 4;
    }

    float acc[4][4][4];
#pragma unroll
    for (int mf = 0; mf < 4; mf++)
#pragma unroll
        for (int nf = 0; nf < 4; nf++)
#pragma unroll
            for (int e = 0; e < 4; e++) acc[mf][nf][e] = 0.f;

    // prologue: stage chunks 0,1
#pragma unroll
    for (int i = 0; i < 4; i++) CP_ASYNC16(saA[i], gpA[i]);
#pragma unroll
    for (int i = 0; i < 4; i++) CP_ASYNC16(saB[i], gpB[i]);
    CP_COMMIT();
#pragma unroll
    for (int i = 0; i < 4; i++) CP_ASYNC16(saA[i] + A_BUF * 4, gpA[i] + 32);
#pragma unroll
    for (int i = 0; i < 4; i++) CP_ASYNC16(saB[i] + B_BUF * 4, gpB[i] + 32 * DIM);
    CP_COMMIT();

    const int ar = lane >> 2, ac = lane & 3;

#pragma unroll 1
    for (int t = 0; t < KCHUNKS; t++) {
        const int buf = t % 3;
        if (t + 2 < KCHUNKS) {
            const int nb = (t + 2) % 3;
            const uint32_t dA = nb * A_BUF * 4, dB = nb * B_BUF * 4;
#pragma unroll
            for (int i = 0; i < 4; i++) CP_ASYNC16(saA[i] + dA, gpA[i] + (t + 2) * 32);
#pragma unroll
            for (int i = 0; i < 4; i++) CP_ASYNC16(saB[i] + dB, gpB[i] + (t + 2) * 32 * DIM);
            CP_COMMIT();
            CP_WAIT(2);
        } else if (t + 1 < KCHUNKS) {
            CP_WAIT(1);
        } else {
            CP_WAIT(0);
        }
        __syncthreads();

        const uint32_t* As = (const uint32_t*)(sm + OFF_A(buf));
        const uint32_t* Bs = (const uint32_t*)(sm + OFF_B(buf));

#pragma unroll
        for (int kk = 0; kk < 32; kk += 8) {
            uint32_t a[4][4], b[4][2];
#pragma unroll
            for (int mf = 0; mf < 4; mf++) {
                int r = (wm * 64 + mf * 16 + ar) * PITCH_A;
                a[mf][0] = As[r + kk + ac];
                a[mf][1] = As[r + 8 * PITCH_A + kk + ac];
                a[mf][2] = As[r + kk + ac + 4];
                a[mf][3] = As[r + 8 * PITCH_A + kk + ac + 4];
            }
#pragma unroll
            for (int nf = 0; nf < 4; nf++) {
                int n = wn * 32 + nf * 8 + ar;
                b[nf][0] = Bs[(kk + ac) * PITCH_B + n];
                b[nf][1] = Bs[(kk + ac + 4) * PITCH_B + n];
            }
#pragma unroll
            for (int mf = 0; mf < 4; mf++)
#pragma unroll
                for (int nf = 0; nf < 4; nf++)
                    mma_tf32(acc[mf][nf][0], acc[mf][nf][1], acc[mf][nf][2], acc[mf][nf][3],
                             a[mf][0], a[mf][1], a[mf][2], a[mf][3],
                             b[nf][0], b[nf][1]);
        }
        __syncthreads();
    }

    // epilogue
#pragma unroll
    for (int mf = 0; mf < 4; mf++) {
#pragma unroll
        for (int nf = 0; nf < 4; nf++) {
            int m = m0 + wm * 64 + mf * 16 + ar;
            int n = n0 + wn * 32 + nf * 8 + ac * 2;
            if (MODE == 0) {
                float2 lo = make_float2(f_rna_tf32(acc[mf][nf][0]), f_rna_tf32(acc[mf][nf][1]));
                float2 hi = make_float2(f_rna_tf32(acc[mf][nf][2]), f_rna_tf32(acc[mf][nf][3]));
                int h = n >> 6, dd = n & 63;
                int bb0 = m >> 10, s0 = m & 1023;
                int bb1 = (m + 8) >> 10, s1 = (m + 8) & 1023;
                *(float2*)&dst[(((bb0 * NH + h) * SEQ) + s0) * HD + dd] = lo;
                *(float2*)&dst[(((bb1 * NH + h) * SEQ) + s1) * HD + dd] = hi;
            } else {
                float2 lo = make_float2(acc[mf][nf][0], acc[mf][nf][1]);
                float2 hi = make_float2(acc[mf][nf][2], acc[mf][nf][3]);
                *(float2*)&dst[m * DIM + n] = lo;
                *(float2*)&dst[(m + 8) * DIM + n] = hi;
            }
        }
    }
}

// -------------------- tensor-core flash attention ---------------------------
// Block = (qtile 128, h, b), 256 threads = 8 warps, warp owns 16 q-rows.
// S = Q K^T native row.col (A=Q [q][d], B=K [k][d]).
// PV uses g_vt: B = V^T [d][s] native. P: acc-frag -> A-frag via quad shfls.
// Smem floats: sQ[128*68=8704] | sK[2][4352] | sVt[2][4352] = 26112 (104448 B).
#define AP 68
#define ATTN_K0 8704
#define ATTN_V0 17408
#define ATTN_SMEM_BYTES (26112 * 4)

__global__ __launch_bounds__(256) void attn_tc(const int* __restrict__ vlens)
{
    extern __shared__ float sm[];
    const uint32_t sb = smem_u32(sm);
    const int tid = threadIdx.x, lane = tid & 31, wq = tid >> 5;
    const int qt = blockIdx.x, h = blockIdx.y, b = blockIdx.z;
    const int vlen = vlens[b];
    const int ntiles = (vlen + 63) >> 6;

    const float* qb  = g_q  + ((size_t)(b * NH + h) * SEQ + qt * 128) * HD;
    const float* kb  = g_k  + ((size_t)(b * NH + h) * SEQ) * HD;
    const float* vtb = g_vt + ((size_t)(b * NH + h) * HD) * SEQ;

    // stage Q (128 rows)
#pragma unroll
    for (int i = 0; i < 8; i++) {
        int idx = tid + i * 256, r = idx >> 4, c4 = (idx & 15) * 4;
        CP_ASYNC16(sb + (r * AP + c4) * 4, qb + r * HD + c4);
    }
    // stage K0 / Vt0 into buffer 0
#pragma unroll
    for (int i = 0; i < 4; i++) {
        int idx = tid + i * 256, r = idx >> 4, c4 = (idx & 15) * 4;
        CP_ASYNC16(sb + (ATTN_K0 + r * AP + c4) * 4, kb + r * HD + c4);
        CP_ASYNC16(sb + (ATTN_V0 + r * AP + c4) * 4, vtb + r * SEQ + c4);
    }
    CP_COMMIT();

    float m_run[2] = {-1e30f, -1e30f};
    float l_run[2] = {0.f, 0.f};
    float oAcc[8][4];
#pragma unroll
    for (int nf = 0; nf < 8; nf++)
#pragma unroll
        for (int e = 0; e < 4; e++) oAcc[nf][e] = 0.f;

    const int lr = lane >> 2, lc = lane & 3;
    const int qrow = wq * 16 + lr;

#pragma unroll 1
    for (int kt = 0; kt < ntiles; kt++) {
        if (kt + 1 < ntiles) {
            const int nb = (kt + 1) & 1;
#pragma unroll
            for (int i = 0; i < 4; i++) {
                int idx = tid + i * 256, r = idx >> 4, c4 = (idx & 15) * 4;
                CP_ASYNC16(sb + (ATTN_K0 + nb * 4352 + r * AP + c4) * 4,
                           kb + ((kt + 1) * 64 + r) * HD + c4);
                CP_ASYNC16(sb + (ATTN_V0 + nb * 4352 + r * AP + c4) * 4,
                           vtb + r * SEQ + (kt + 1) * 64 + c4);
            }
            CP_COMMIT();
            CP_WAIT(1);
        } else {
            CP_WAIT(0);
        }
        __syncthreads();

        const uint32_t* Qs = (const uint32_t*)sm;
        const uint32_t* Ks = (const uint32_t*)(sm + ATTN_K0 + (kt & 1) * 4352);
        const uint32_t* Vs = (const uint32_t*)(sm + ATTN_V0 + (kt & 1) * 4352);

        // ---- S = Q K^T ----
        float sAcc[8][4];
#pragma unroll
        for (int nf = 0; nf < 8; nf++)
#pragma unroll
            for (int e = 0; e < 4; e++) sAcc[nf][e] = 0.f;

#pragma unroll
        for (int kk = 0; kk < 64; kk += 8) {
            uint32_t a0 = Qs[qrow * AP + kk + lc];
            uint32_t a1 = Qs[(qrow + 8) * AP + kk + lc];
            uint32_t a2 = Qs[qrow * AP + kk + lc + 4];
            uint32_t a3 = Qs[(qrow + 8) * AP + kk + lc + 4];
#pragma unroll
            for (int nf = 0; nf < 8; nf++) {
                int n = nf * 8 + lr;
                uint32_t b0 = Ks[n * AP + kk + lc];
                uint32_t b1 = Ks[n * AP + kk + lc + 4];
                mma_tf32(sAcc[nf][0], sAcc[nf][1], sAcc[nf][2], sAcc[nf][3],
                         a0, a1, a2, a3, b0, b1);
            }
        }

        // ---- mask + scale + fragment softmax ----
        float rmax0 = -1e30f, rmax1 = -1e30f;
#pragma unroll
        for (int nf = 0; nf < 8; nf++) {
#pragma unroll
            for (int e = 0; e < 2; e++) {
                int col = kt * 64 + nf * 8 + 2 * lc + e;
                bool ok = col < vlen;
                sAcc[nf][e]     = ok ? sAcc[nf][e] * 0.125f     : -1e6f;
                sAcc[nf][2 + e] = ok ? sAcc[nf][2 + e] * 0.125f : -1e6f;
                rmax0 = fmaxf(rmax0, sAcc[nf][e]);
                rmax1 = fmaxf(rmax1, sAcc[nf][2 + e]);
            }
        }
        rmax0 = fmaxf(rmax0, __shfl_xor_sync(0xffffffffu, rmax0, 1));
        rmax0 = fmaxf(rmax0, __shfl_xor_sync(0xffffffffu, rmax0, 2));
        rmax1 = fmaxf(rmax1, __shfl_xor_sync(0xffffffffu, rmax1, 1));
        rmax1 = fmaxf(rmax1, __shfl_xor_sync(0xffffffffu, rmax1, 2));

        float nm0 = fmaxf(m_run[0], rmax0), nm1 = fmaxf(m_run[1], rmax1);
        float alpha0 = __expf(m_run[0] - nm0), alpha1 = __expf(m_run[1] - nm1);
        m_run[0] = nm0; m_run[1] = nm1;

        float ts0 = 0.f, ts1 = 0.f;
#pragma unroll
        for (int nf = 0; nf < 8; nf++) {
#pragma unroll
            for (int e = 0; e < 2; e++) {
                float p0 = f_rna_tf32(__expf(sAcc[nf][e] - nm0));
                float p1 = f_rna_tf32(__expf(sAcc[nf][2 + e] - nm1));
                ts0 += p0; ts1 += p1;
                sAcc[nf][e] = p0; sAcc[nf][2 + e] = p1;
            }
        }
        ts0 += __shfl_xor_sync(0xffffffffu, ts0, 1);
        ts0 += __shfl_xor_sync(0xffffffffu, ts0, 2);
        ts1 += __shfl_xor_sync(0xffffffffu, ts1, 1);
        ts1 += __shfl_xor_sync(0xffffffffu, ts1, 2);
        l_run[0] = l_run[0] * alpha0 + ts0;
        l_run[1] = l_run[1] * alpha1 + ts1;

#pragma unroll
        for (int nf = 0; nf < 8; nf++) {
            oAcc[nf][0] *= alpha0; oAcc[nf][1] *= alpha0;
            oAcc[nf][2] *= alpha1; oAcc[nf][3] *= alpha1;
        }

        // ---- O += P V : P acc-frag -> A-frag via quad shfl ----
        const int srcA = (lane & ~3) | (lc >> 1);
        const int srcB = srcA + 2;
        const bool oddc = lc & 1;
#pragma unroll
        for (int kc = 0; kc < 8; kc++) {
            float v0 = __shfl_sync(0xffffffffu, sAcc[kc][0], srcA);
            float v1 = __shfl_sync(0xffffffffu, sAcc[kc][1], srcA);
            float v2 = __shfl_sync(0xffffffffu, sAcc[kc][2], srcA);
            float v3 = __shfl_sync(0xffffffffu, sAcc[kc][3], srcA);
            float u0 = __shfl_sync(0xffffffffu, sAcc[kc][0], srcB);
            float u1 = __shfl_sync(0xffffffffu, sAcc[kc][1], srcB);
            float u2 = __shfl_sync(0xffffffffu, sAcc[kc][2], srcB);
            float u3 = __shfl_sync(0xffffffffu, sAcc[kc][3], srcB);
            uint32_t a0 = __float_as_uint(oddc ? v1 : v0);
            uint32_t a1 = __float_as_uint(oddc ? v3 : v2);
            uint32_t a2 = __float_as_uint(oddc ? u1 : u0);
            uint32_t a3 = __float_as_uint(oddc ? u3 : u2);
#pragma unroll
            for (int nf = 0; nf < 8; nf++) {
                int n = nf * 8 + lr;
                uint32_t b0 = Vs[n * AP + kc * 8 + lc];
                uint32_t b1 = Vs[n * AP + kc * 8 + lc + 4];
                mma_tf32(oAcc[nf][0], oAcc[nf][1], oAcc[nf][2], oAcc[nf][3],
                         a0, a1, a2, a3, b0, b1);
            }
        }
        __syncthreads();
    }

    // ---- epilogue: normalize, round, store ctx ----
    float inv0 = 1.f / l_run[0], inv1 = 1.f / l_run[1];
    int row0 = qt * 128 + wq * 16 + lr;
    int row1 = row0 + 8;
#pragma unroll
    for (int nf = 0; nf < 8; nf++) {
        int col = h * HD + nf * 8 + 2 * lc;
        float2 lo = make_float2(f_rna_tf32(oAcc[nf][0] * inv0), f_rna_tf32(oAcc[nf][1] * inv0));
        float2 hi = make_float2(f_rna_tf32(oAcc[nf][2] * inv1), f_rna_tf32(oAcc[nf][3] * inv1));
        *(float2*)&g_ctx[(b * SEQ + row0) * DIM + col] = lo;
        *(float2*)&g_ctx[(b * SEQ + row1) * DIM + col] = hi;
    }
}

// ---------------------------------------------------------------------------
extern "C" void kernel_launch(void* const* d_in, const int* in_sizes, int n_in,
                              void* d_out, int out_size)
{
    const float* queries = (const float*)d_in[0];
    const float* keys    = (const float*)d_in[1];
    const float* values  = (const float*)d_in[2];
    const int*   vlens   = (const int*)d_in[3];
    const float* W_q     = (const float*)d_in[4];
    const float* W_o     = (const float*)d_in[5];
    float* out = (float*)d_out;

    cudaFuncSetAttribute(gemm_mma<0>, cudaFuncAttributeMaxDynamicSharedMemorySize, GEMM_SMEM_BYTES);
    cudaFuncSetAttribute(gemm_mma<1>, cudaFuncAttributeMaxDynamicSharedMemorySize, GEMM_SMEM_BYTES);
    cudaFuncSetAttribute(attn_tc, cudaFuncAttributeMaxDynamicSharedMemorySize, ATTN_SMEM_BYTES);

    prep_rna<<<dim3(512, 5), 256>>>(queries, keys, values, W_q, W_o);
    gemm_mma<0><<<dim3(8, 32, 3), 256, GEMM_SMEM_BYTES>>>(nullptr, vlens);
    transpose_v<<<dim3(SEQ / 32, HD / 32, BATCH * NH), 256>>>(vlens);
    attn_tc<<<dim3(SEQ / 128, NH, BATCH), 256, ATTN_SMEM_BYTES>>>(vlens);
    gemm_mma<1><<<dim3(8, 32, 1), 256, GEMM_SMEM_BYTES>>>(out, vlens);
}

// round 6
// speedup vs baseline: 4.8672x; 1.2195x over previous
#include <cuda_runtime.h>
#include <cstdint>

#define BATCH 4
#define SEQ   1024
#define DIM   1024
#define NH    16
#define HD    64

// -------------------- device scratch (allocation-free) ----------------------
__device__ float g_q[BATCH * NH * SEQ * HD];     // head-split, tf32-rounded, pre-scaled 1/8
__device__ float g_k[BATCH * NH * SEQ * HD];
__device__ float g_v[BATCH * NH * SEQ * HD];
__device__ float g_vt[BATCH * NH * HD * SEQ];    // V transposed [b,h,d,s]
__device__ float g_ctx[BATCH * SEQ * DIM];       // attn output (tf32-rna rounded)
__device__ float g_qr[BATCH * SEQ * DIM];        // rna-rounded inputs
__device__ float g_kr[BATCH * SEQ * DIM];
__device__ float g_vr[BATCH * SEQ * DIM];
__device__ float g_wqt[DIM * DIM];               // W_q^T rounded, [n][k]
__device__ float g_wot[DIM * DIM];               // W_o^T rounded, [n][k]

// -------------------- helpers ----------------------------------------------
__device__ __forceinline__ uint32_t smem_u32(const void* p) {
    uint32_t a;
    asm("{ .reg .u64 t; cvta.to.shared.u64 t, %1; cvt.u32.u64 %0, t; }" : "=r"(a) : "l"(p));
    return a;
}
__device__ __forceinline__ float f_rna_tf32(float f) {
    uint32_t r; asm("cvt.rna.tf32.f32 %0, %1;" : "=r"(r) : "f"(f));
    return __uint_as_float(r);
}

#define CP_ASYNC16(sa, gp) \
    asm volatile("cp.async.cg.shared.global [%0], [%1], 16;" :: "r"(sa), "l"(gp))
#define CP_COMMIT() asm volatile("cp.async.commit_group;" ::: "memory")
#define CP_WAIT(n)  asm volatile("cp.async.wait_group %0;" :: "n"(n) : "memory")

#define LDSM_X4(r0, r1, r2, r3, a) \
    asm volatile("ldmatrix.sync.aligned.m8n8.x4.shared.b16 {%0,%1,%2,%3}, [%4];" \
                 : "=r"(r0), "=r"(r1), "=r"(r2), "=r"(r3) : "r"(a))

__device__ __forceinline__ void mma_tf32(float& d0, float& d1, float& d2, float& d3,
                                         uint32_t a0, uint32_t a1, uint32_t a2, uint32_t a3,
                                         uint32_t b0, uint32_t b1) {
    asm volatile(
        "mma.sync.aligned.m16n8k8.row.col.f32.tf32.tf32.f32 "
        "{%0,%1,%2,%3}, {%4,%5,%6,%7}, {%8,%9}, {%0,%1,%2,%3};"
        : "+f"(d0), "+f"(d1), "+f"(d2), "+f"(d3)
        : "r"(a0), "r"(a1), "r"(a2), "r"(a3), "r"(b0), "r"(b1));
}

// -------------------- prep: rna-round q/k/v (vlen-skip for k/v) -------------
__global__ void prep_rna(const float* __restrict__ q, const float* __restrict__ k,
                         const float* __restrict__ v, const int* __restrict__ vlens)
{
    const int y = blockIdx.y;
    const float* src = (y == 0) ? q : (y == 1) ? k : v;
    float* dst = (y == 0) ? g_qr : (y == 1) ? g_kr : g_vr;
    const int n4 = (BATCH * SEQ * DIM) / 4;
    for (int i = blockIdx.x * blockDim.x + threadIdx.x; i < n4; i += gridDim.x * blockDim.x) {
        if (y != 0) {
            int e = i * 4;
            int b = e >> 20;              // SEQ*DIM = 2^20
            int s = (e >> 10) & (SEQ - 1);
            if (s >= vlens[b]) continue;  // masked rows never influence output
        }
        float4 x = ((const float4*)src)[i];
        x.x = f_rna_tf32(x.x); x.y = f_rna_tf32(x.y);
        x.z = f_rna_tf32(x.z); x.w = f_rna_tf32(x.w);
        ((float4*)dst)[i] = x;
    }
}

// -------------------- prep: transpose + round weights -----------------------
__global__ void prep_wt(const float* __restrict__ Wq, const float* __restrict__ Wo)
{
    const float* src = blockIdx.z ? Wo : Wq;
    float* dst = blockIdx.z ? g_wot : g_wqt;
    __shared__ float t[32][33];
    const int tid = threadIdx.x;
    const int n0 = blockIdx.x * 32, k0 = blockIdx.y * 32;
#pragma unroll
    for (int i = 0; i < 4; i++) {
        int idx = tid + i * 256, r = idx >> 5, c = idx & 31;
        t[r][c] = src[(k0 + r) * DIM + n0 + c];
    }
    __syncthreads();
#pragma unroll
    for (int i = 0; i < 4; i++) {
        int idx = tid + i * 256, r = idx >> 5, c = idx & 31;  // r=n, c=k
        dst[(n0 + r) * DIM + k0 + c] = f_rna_tf32(t[c][r]);
    }
}

// -------------------- V transpose: [bh,s,d] -> [bh,d,s] (vlen-skipped) ------
__global__ void transpose_v(const int* __restrict__ vlens)
{
    __shared__ float t[32][33];
    const int tid = threadIdx.x;
    const int s0 = blockIdx.x * 32, d0 = blockIdx.y * 32, z = blockIdx.z;
    if (s0 >= vlens[z / NH]) return;
    const float* src = g_v + (size_t)z * SEQ * HD;
    float* dst = g_vt + (size_t)z * HD * SEQ;
#pragma unroll
    for (int i = 0; i < 4; i++) {
        int idx = tid + i * 256, r = idx >> 5, c = idx & 31;
        t[r][c] = src[(s0 + r) * HD + d0 + c];
    }
    __syncthreads();
#pragma unroll
    for (int i = 0; i < 4; i++) {
        int idx = tid + i * 256, r = idx >> 5, c = idx & 31;
        dst[(d0 + r) * SEQ + s0 + c] = t[c][r];
    }
}

// -------------------- tf32 mma.sync GEMM, ldmatrix operand loads ------------
// 128x128 tile, BK=32, 256 thr (8 warps 2x4), warp tile 64x32.
// A [m][k] pitch 36; B [n][k] pitch 36 (weights pre-transposed). Row stride
// 144B = 9 x 16B (odd mod 8) => LDSM conflict-free.
#define PITCH 36
#define AB_BUF (128 * PITCH)                 // 4608 floats per operand stage
#define GEMM_SMEM_BYTES (6 * AB_BUF * 4)     // 110592: 3-stage A + 3-stage B
#define KCHUNKS 32

// MODE 0: proj (z: g_qr/g_kr/g_vr @ g_wqt -> g_q/g_k/g_v; z==0 pre-scaled 1/8)
// MODE 1: out  (g_ctx @ g_wot -> outp plain)
template<int MODE>
__global__ __launch_bounds__(256, 2) void gemm_mma(float* __restrict__ outp,
                                                   const int* __restrict__ vlens)
{
    extern __shared__ float sm[];
    const uint32_t sb = smem_u32(sm);
    const int tid = threadIdx.x, lane = tid & 31, wid = tid >> 5;
    const int wm = wid >> 2, wn = wid & 3;
    const int m0 = blockIdx.y * 128, n0 = blockIdx.x * 128;
    const int z = (MODE == 0) ? blockIdx.z : 0;

    const float* A; const float* B; float* dst;
    if (MODE == 0) {
        A   = (z == 0) ? g_qr : (z == 1) ? g_kr : g_vr;
        dst = (z == 0) ? g_q  : (z == 1) ? g_k  : g_v;
        B   = g_wqt;
        if (z != 0 && (m0 & (SEQ - 1)) >= vlens[m0 >> 10]) return;
    } else {
        A = g_ctx; dst = outp; B = g_wot;
    }

    // staging (identical pattern for A and B: 128 rows x 8 16B-chunks)
    uint32_t saA[4], saB[4];
    const float* gpA[4]; const float* gpB[4];
#pragma unroll
    for (int i = 0; i < 4; i++) {
        int s = tid + i * 256;
        int r = s >> 3, c = s & 7;
        saA[i] = sb + (r * PITCH + c * 4) * 4;
        saB[i] = sb + (3 * AB_BUF + r * PITCH + c * 4) * 4;
        gpA[i] = A + (m0 + r) * DIM + c * 4;
        gpB[i] = B + (n0 + r) * DIM + c * 4;
    }

    // ldmatrix lane bases (bytes)
    const uint32_t laneA = ((lane & 15) * PITCH + ((lane >> 4) << 2)) * 4;
    const uint32_t laneB = (((lane & 7) + ((lane & 16) ? 8 : 0)) * PITCH +
                            ((lane & 8) ? 4 : 0)) * 4;
    uint32_t aBase[4], bBase[2];
#pragma unroll
    for (int mf = 0; mf < 4; mf++) aBase[mf] = (wm * 64 + mf * 16) * PITCH * 4 + laneA;
#pragma unroll
    for (int p = 0; p < 2; p++)
        bBase[p] = 3 * AB_BUF * 4 + (wn * 32 + p * 16) * PITCH * 4 + laneB;

    float acc[4][4][4];
#pragma unroll
    for (int mf = 0; mf < 4; mf++)
#pragma unroll
        for (int nf = 0; nf < 4; nf++)
#pragma unroll
            for (int e = 0; e < 4; e++) acc[mf][nf][e] = 0.f;

    // prologue: stage chunks 0,1
#pragma unroll
    for (int i = 0; i < 4; i++) CP_ASYNC16(saA[i], gpA[i]);
#pragma unroll
    for (int i = 0; i < 4; i++) CP_ASYNC16(saB[i], gpB[i]);
    CP_COMMIT();
#pragma unroll
    for (int i = 0; i < 4; i++) CP_ASYNC16(saA[i] + AB_BUF * 4, gpA[i] + 32);
#pragma unroll
    for (int i = 0; i < 4; i++) CP_ASYNC16(saB[i] + AB_BUF * 4, gpB[i] + 32);
    CP_COMMIT();

#pragma unroll 1
    for (int t = 0; t < KCHUNKS; t++) {
        if (t == KCHUNKS - 1) { CP_WAIT(0); } else { CP_WAIT(1); }
        __syncthreads();
        if (t + 2 < KCHUNKS) {
            const uint32_t d = ((t + 2) % 3) * AB_BUF * 4;
#pragma unroll
            for (int i = 0; i < 4; i++) CP_ASYNC16(saA[i] + d, gpA[i] + (t + 2) * 32);
#pragma unroll
            for (int i = 0; i < 4; i++) CP_ASYNC16(saB[i] + d, gpB[i] + (t + 2) * 32);
            CP_COMMIT();
        }

        const uint32_t bufOff = (t % 3) * AB_BUF * 4;
#pragma unroll
        for (int kk = 0; kk < 32; kk += 8) {
            uint32_t a[4][4], bf[2][4];
#pragma unroll
            for (int mf = 0; mf < 4; mf++)
                LDSM_X4(a[mf][0], a[mf][1], a[mf][2], a[mf][3],
                        sb + bufOff + aBase[mf] + kk * 4);
#pragma unroll
            for (int p = 0; p < 2; p++)
                LDSM_X4(bf[p][0], bf[p][1], bf[p][2], bf[p][3],
                        sb + bufOff + bBase[p] + kk * 4);
#pragma unroll
            for (int mf = 0; mf < 4; mf++)
#pragma unroll
                for (int nf = 0; nf < 4; nf++)
                    mma_tf32(acc[mf][nf][0], acc[mf][nf][1], acc[mf][nf][2], acc[mf][nf][3],
                             a[mf][0], a[mf][1], a[mf][2], a[mf][3],
                             bf[nf >> 1][(nf & 1) * 2], bf[nf >> 1][(nf & 1) * 2 + 1]);
        }
    }

    // epilogue
    const int ar = lane >> 2, ac = lane & 3;
    const float qs = (MODE == 0 && z == 0) ? 0.125f : 1.0f;
#pragma unroll
    for (int mf = 0; mf < 4; mf++) {
#pragma unroll
        for (int nf = 0; nf < 4; nf++) {
            int m = m0 + wm * 64 + mf * 16 + ar;
            int n = n0 + wn * 32 + nf * 8 + ac * 2;
            if (MODE == 0) {
                float2 lo = make_float2(f_rna_tf32(acc[mf][nf][0] * qs),
                                        f_rna_tf32(acc[mf][nf][1] * qs));
                float2 hi = make_float2(f_rna_tf32(acc[mf][nf][2] * qs),
                                        f_rna_tf32(acc[mf][nf][3] * qs));
                int h = n >> 6, dd = n & 63;
                int bb0 = m >> 10, s0 = m & 1023;
                int bb1 = (m + 8) >> 10, s1 = (m + 8) & 1023;
                *(float2*)&dst[(((bb0 * NH + h) * SEQ) + s0) * HD + dd] = lo;
                *(float2*)&dst[(((bb1 * NH + h) * SEQ) + s1) * HD + dd] = hi;
            } else {
                *(float2*)&dst[m * DIM + n] =
                    make_float2(acc[mf][nf][0], acc[mf][nf][1]);
                *(float2*)&dst[(m + 8) * DIM + n] =
                    make_float2(acc[mf][nf][2], acc[mf][nf][3]);
            }
        }
    }
}

// -------------------- tensor-core flash attention (ldmatrix) ----------------
// Block = (qtile 128, h, b), 256 threads = 8 warps, warp owns 16 q-rows.
// Q pre-scaled by 1/8, so sAcc are final scores. Mask only on last tile.
// Smem floats: sQ[128*68] | sK[2][64*68] | sVt[2][64*68]; pitch 68 -> row
// stride 272B = 17 x 16B (odd mod 8) => LDSM conflict-free.
#define AP 68
#define ATTN_K0 8704
#define ATTN_V0 17408
#define ATTN_SMEM_BYTES (26112 * 4)

__global__ __launch_bounds__(256) void attn_tc(const int* __restrict__ vlens)
{
    extern __shared__ float sm[];
    const uint32_t sb = smem_u32(sm);
    const int tid = threadIdx.x, lane = tid & 31, wq = tid >> 5;
    const int qt = blockIdx.x, h = blockIdx.y, b = blockIdx.z;
    const int vlen = vlens[b];
    const int ntiles = (vlen + 63) >> 6;

    const float* qb  = g_q  + ((size_t)(b * NH + h) * SEQ + qt * 128) * HD;
    const float* kb  = g_k  + ((size_t)(b * NH + h) * SEQ) * HD;
    const float* vtb = g_vt + ((size_t)(b * NH + h) * HD) * SEQ;

    // stage Q (128 rows) + K0/Vt0 (one group)
#pragma unroll
    for (int i = 0; i < 8; i++) {
        int idx = tid + i * 256, r = idx >> 4, c4 = (idx & 15) * 4;
        CP_ASYNC16(sb + (r * AP + c4) * 4, qb + r * HD + c4);
    }
#pragma unroll
    for (int i = 0; i < 4; i++) {
        int idx = tid + i * 256, r = idx >> 4, c4 = (idx & 15) * 4;
        CP_ASYNC16(sb + (ATTN_K0 + r * AP + c4) * 4, kb + r * HD + c4);
        CP_ASYNC16(sb + (ATTN_V0 + r * AP + c4) * 4, vtb + r * SEQ + c4);
    }
    CP_COMMIT();

    // ldmatrix lane bases (bytes)
    const uint32_t laneQ = ((lane & 15) * AP + ((lane >> 4) << 2)) * 4;
    const uint32_t laneP8 = (((lane & 7) + ((lane & 16) ? 8 : 0)) * AP +
                             ((lane & 8) ? 4 : 0)) * 4;
    const uint32_t qBase = wq * 16 * AP * 4 + laneQ;
    uint32_t pPair[4];
#pragma unroll
    for (int p = 0; p < 4; p++) pPair[p] = p * 16 * AP * 4 + laneP8;

    float m_run[2] = {-1e30f, -1e30f};
    float l_run[2] = {0.f, 0.f};
    float oAcc[8][4];
#pragma unroll
    for (int nf = 0; nf < 8; nf++)
#pragma unroll
        for (int e = 0; e < 4; e++) oAcc[nf][e] = 0.f;

    const int lr = lane >> 2, lc = lane & 3;

#pragma unroll 1
    for (int kt = 0; kt < ntiles; kt++) {
        CP_WAIT(0);
        __syncthreads();
        if (kt + 1 < ntiles) {
            const int nb = (kt + 1) & 1;
#pragma unroll
            for (int i = 0; i < 4; i++) {
                int idx = tid + i * 256, r = idx >> 4, c4 = (idx & 15) * 4;
                CP_ASYNC16(sb + (ATTN_K0 + nb * 4352 + r * AP + c4) * 4,
                           kb + ((kt + 1) * 64 + r) * HD + c4);
                CP_ASYNC16(sb + (ATTN_V0 + nb * 4352 + r * AP + c4) * 4,
                           vtb + r * SEQ + (kt + 1) * 64 + c4);
            }
            CP_COMMIT();
        }

        const uint32_t kBuf = (ATTN_K0 + (kt & 1) * 4352) * 4;
        const uint32_t vBuf = (ATTN_V0 + (kt & 1) * 4352) * 4;

        // ---- S = Q K^T (scores already scaled: Q premultiplied by 1/8) ----
        float sAcc[8][4];
#pragma unroll
        for (int nf = 0; nf < 8; nf++)
#pragma unroll
            for (int e = 0; e < 4; e++) sAcc[nf][e] = 0.f;

#pragma unroll
        for (int kk = 0; kk < 64; kk += 8) {
            uint32_t a0, a1, a2, a3, kf[4][4];
            LDSM_X4(a0, a1, a2, a3, sb + qBase + kk * 4);
#pragma unroll
            for (int p = 0; p < 4; p++)
                LDSM_X4(kf[p][0], kf[p][1], kf[p][2], kf[p][3],
                        sb + kBuf + pPair[p] + kk * 4);
#pragma unroll
            for (int nf = 0; nf < 8; nf++)
                mma_tf32(sAcc[nf][0], sAcc[nf][1], sAcc[nf][2], sAcc[nf][3],
                         a0, a1, a2, a3,
                         kf[nf >> 1][(nf & 1) * 2], kf[nf >> 1][(nf & 1) * 2 + 1]);
        }

        // ---- mask (last tile only) ----
        if (kt == ntiles - 1 && (vlen & 63)) {
#pragma unroll
            for (int nf = 0; nf < 8; nf++) {
#pragma unroll
                for (int e = 0; e < 2; e++) {
                    int col = kt * 64 + nf * 8 + 2 * lc + e;
                    if (col >= vlen) { sAcc[nf][e] = -1e6f; sAcc[nf][2 + e] = -1e6f; }
                }
            }
        }

        // ---- fragment online softmax ----
        float rmax0 = -1e30f, rmax1 = -1e30f;
#pragma unroll
        for (int nf = 0; nf < 8; nf++) {
            rmax0 = fmaxf(rmax0, fmaxf(sAcc[nf][0], sAcc[nf][1]));
            rmax1 = fmaxf(rmax1, fmaxf(sAcc[nf][2], sAcc[nf][3]));
        }
        rmax0 = fmaxf(rmax0, __shfl_xor_sync(0xffffffffu, rmax0, 1));
        rmax0 = fmaxf(rmax0, __shfl_xor_sync(0xffffffffu, rmax0, 2));
        rmax1 = fmaxf(rmax1, __shfl_xor_sync(0xffffffffu, rmax1, 1));
        rmax1 = fmaxf(rmax1, __shfl_xor_sync(0xffffffffu, rmax1, 2));

        float nm0 = fmaxf(m_run[0], rmax0), nm1 = fmaxf(m_run[1], rmax1);
        float alpha0 = __expf(m_run[0] - nm0), alpha1 = __expf(m_run[1] - nm1);
        m_run[0] = nm0; m_run[1] = nm1;

        float ts0 = 0.f, ts1 = 0.f;
#pragma unroll
        for (int nf = 0; nf < 8; nf++) {
#pragma unroll
            for (int e = 0; e < 2; e++) {
                float p0 = f_rna_tf32(__expf(sAcc[nf][e] - nm0));
                float p1 = f_rna_tf32(__expf(sAcc[nf][2 + e] - nm1));
                ts0 += p0; ts1 += p1;
                sAcc[nf][e] = p0; sAcc[nf][2 + e] = p1;
            }
        }
        ts0 += __shfl_xor_sync(0xffffffffu, ts0, 1);
        ts0 += __shfl_xor_sync(0xffffffffu, ts0, 2);
        ts1 += __shfl_xor_sync(0xffffffffu, ts1, 1);
        ts1 += __shfl_xor_sync(0xffffffffu, ts1, 2);
        l_run[0] = l_run[0] * alpha0 + ts0;
        l_run[1] = l_run[1] * alpha1 + ts1;

#pragma unroll
        for (int nf = 0; nf < 8; nf++) {
            oAcc[nf][0] *= alpha0; oAcc[nf][1] *= alpha0;
            oAcc[nf][2] *= alpha1; oAcc[nf][3] *= alpha1;
        }

        // ---- O += P V ----
        const int srcA = (lane & ~3) | (lc >> 1);
        const int srcB = srcA + 2;
        const bool oddc = lc & 1;
#pragma unroll
        for (int kc = 0; kc < 8; kc++) {
            float v0 = __shfl_sync(0xffffffffu, sAcc[kc][0], srcA);
            float v1 = __shfl_sync(0xffffffffu, sAcc[kc][1], srcA);
            float v2 = __shfl_sync(0xffffffffu, sAcc[kc][2], srcA);
            float v3 = __shfl_sync(0xffffffffu, sAcc[kc][3], srcA);
            float u0 = __shfl_sync(0xffffffffu, sAcc[kc][0], srcB);
            float u1 = __shfl_sync(0xffffffffu, sAcc[kc][1], srcB);
            float u2 = __shfl_sync(0xffffffffu, sAcc[kc][2], srcB);
            float u3 = __shfl_sync(0xffffffffu, sAcc[kc][3], srcB);
            uint32_t a0 = __float_as_uint(oddc ? v1 : v0);
            uint32_t a1 = __float_as_uint(oddc ? v3 : v2);
            uint32_t a2 = __float_as_uint(oddc ? u1 : u0);
            uint32_t a3 = __float_as_uint(oddc ? u3 : u2);
            uint32_t vf[4][4];
#pragma unroll
            for (int p = 0; p < 4; p++)
                LDSM_X4(vf[p][0], vf[p][1], vf[p][2], vf[p][3],
                        sb + vBuf + pPair[p] + kc * 32);
#pragma unroll
            for (int nf = 0; nf < 8; nf++)
                mma_tf32(oAcc[nf][0], oAcc[nf][1], oAcc[nf][2], oAcc[nf][3],
                         a0, a1, a2, a3,
                         vf[nf >> 1][(nf & 1) * 2], vf[nf >> 1][(nf & 1) * 2 + 1]);
        }
    }

    // ---- epilogue ----
    float inv0 = 1.f / l_run[0], inv1 = 1.f / l_run[1];
    int row0 = qt * 128 + wq * 16 + lr;
    int row1 = row0 + 8;
#pragma unroll
    for (int nf = 0; nf < 8; nf++) {
        int col = h * HD + nf * 8 + 2 * lc;
        float2 lo = make_float2(f_rna_tf32(oAcc[nf][0] * inv0), f_rna_tf32(oAcc[nf][1] * inv0));
        float2 hi = make_float2(f_rna_tf32(oAcc[nf][2] * inv1), f_rna_tf32(oAcc[nf][3] * inv1));
        *(float2*)&g_ctx[(b * SEQ + row0) * DIM + col] = lo;
        *(float2*)&g_ctx[(b * SEQ + row1) * DIM + col] = hi;
    }
}

// ---------------------------------------------------------------------------
extern "C" void kernel_launch(void* const* d_in, const int* in_sizes, int n_in,
                              void* d_out, int out_size)
{
    const float* queries = (const float*)d_in[0];
    const float* keys    = (const float*)d_in[1];
    const float* values  = (const float*)d_in[2];
    const int*   vlens   = (const int*)d_in[3];
    const float* W_q     = (const float*)d_in[4];
    const float* W_o     = (const float*)d_in[5];
    float* out = (float*)d_out;

    cudaFuncSetAttribute(gemm_mma<0>, cudaFuncAttributeMaxDynamicSharedMemorySize, GEMM_SMEM_BYTES);
    cudaFuncSetAttribute(gemm_mma<1>, cudaFuncAttributeMaxDynamicSharedMemorySize, GEMM_SMEM_BYTES);
    cudaFuncSetAttribute(attn_tc, cudaFuncAttributeMaxDynamicSharedMemorySize, ATTN_SMEM_BYTES);

    prep_rna<<<dim3(512, 3), 256>>>(queries, keys, values, vlens);
    prep_wt<<<dim3(32, 32, 2), 256>>>(W_q, W_o);
    gemm_mma<0><<<dim3(8, 32, 3), 256, GEMM_SMEM_BYTES>>>(nullptr, vlens);
    transpose_v<<<dim3(SEQ / 32, HD / 32, BATCH * NH), 256>>>(vlens);
    attn_tc<<<dim3(SEQ / 128, NH, BATCH), 256, ATTN_SMEM_BYTES>>>(vlens);
    gemm_mma<1><<<dim3(8, 32, 1), 256, GEMM_SMEM_BYTES>>>(out, vlens);
}